// round 1
// baseline (speedup 1.0000x reference)
#include <cuda_runtime.h>
#include <math.h>

// ---------------------------------------------------------------------------
// Problem constants: B=32, H=W=64, C=256, NH=8, hd=32, WS=8, SS=4, IM=4
// Tokens M = 32*64*64 = 131072.  d_ff = 1024.
// ---------------------------------------------------------------------------
#define M_TOK   131072
#define C_DIM   256
#define DFF     1024

// Scratch (device globals; no allocation at runtime)
__device__ float g_xw  [M_TOK * C_DIM];   // LN1 + shift + window-partitioned x
__device__ float g_q   [M_TOK * C_DIM];
__device__ float g_k   [M_TOK * C_DIM];
__device__ float g_v   [M_TOK * C_DIM];
__device__ float g_att [M_TOK * C_DIM];   // attention output (window layout)
__device__ float g_hs  [M_TOK * C_DIM];   // shortcut + attn (token layout)
__device__ float g_y   [M_TOK * C_DIM];   // LN2 output
__device__ float g_mid [M_TOK * DFF];     // MLP intermediate

// ---------------------------------------------------------------------------
// LayerNorm kernel. gather=1: source token is read through inverse
// (roll -4,-4 + window partition) mapping; output row r is window-ordered.
// One block (256 threads) per token; thread c owns channel c.
// ---------------------------------------------------------------------------
__global__ __launch_bounds__(256) void ln_kernel(
    const float* __restrict__ x, const float* __restrict__ g,
    const float* __restrict__ bb, float* __restrict__ out, int gather)
{
    int r = blockIdx.x;
    int c = threadIdx.x;
    long src;
    if (gather) {
        int b  = r >> 12;
        int wi = (r >> 9) & 7, wj = (r >> 6) & 7;
        int pi = (r >> 3) & 7, pj = r & 7;
        int h = (wi * 8 + pi + 4) & 63;   // roll(-4): shifted[sh]=orig[(sh+4)%64]
        int w = (wj * 8 + pj + 4) & 63;
        src = (long)b * 4096 + h * 64 + w;
    } else {
        src = r;
    }
    float v = x[src * C_DIM + c];
    float s = v, s2 = v * v;
    #pragma unroll
    for (int o = 16; o > 0; o >>= 1) {
        s  += __shfl_xor_sync(0xffffffffu, s, o);
        s2 += __shfl_xor_sync(0xffffffffu, s2, o);
    }
    __shared__ float sh[8], sh2[8];
    int warp = c >> 5, lane = c & 31;
    if (lane == 0) { sh[warp] = s; sh2[warp] = s2; }
    __syncthreads();
    float ts = 0.f, ts2 = 0.f;
    #pragma unroll
    for (int wwi = 0; wwi < 8; wwi++) { ts += sh[wwi]; ts2 += sh2[wwi]; }
    float mean = ts * (1.f / 256.f);
    float var  = ts2 * (1.f / 256.f) - mean * mean;
    float rstd = rsqrtf(var + 1e-5f);
    out[(long)r * C_DIM + c] = (v - mean) * rstd * g[c] + bb[c];
}

// ---------------------------------------------------------------------------
// SGEMM: C = epi(A[MxK] @ B[KxN] + bias)  with optional residual / scatter.
// EPI: 0 plain, 1 GELU(exact erf), 2 scatter(window-reverse+roll)+residual,
//      3 residual add (rows aligned).
// 128x128 tile, BK=8, 256 threads, 8x8 per-thread microtile.
// ---------------------------------------------------------------------------
#define BMg 128
#define BNg 128
#define BKg 8

template<int EPI>
__global__ __launch_bounds__(256) void sgemm_kernel(
    const float* __restrict__ A, const float* __restrict__ B,
    const float* __restrict__ bias, const float* __restrict__ R,
    float* __restrict__ C, int M, int N, int K)
{
    __shared__ float As[BKg][BMg];
    __shared__ float Bs[BKg][BNg];

    int tid = threadIdx.x;
    int bm = blockIdx.y * BMg;
    int bn = blockIdx.x * BNg;
    int ty = tid >> 4, tx = tid & 15;

    float acc[8][8];
    #pragma unroll
    for (int i = 0; i < 8; i++)
        #pragma unroll
        for (int j = 0; j < 8; j++) acc[i][j] = 0.f;

    int aRow = tid >> 1, aCol = (tid & 1) * 4;
    int bRow = tid >> 5, bCol = (tid & 31) * 4;

    for (int kb = 0; kb < K; kb += BKg) {
        float4 a4 = *(const float4*)(A + (long)(bm + aRow) * K + kb + aCol);
        float4 b4 = *(const float4*)(B + (long)(kb + bRow) * N + bn + bCol);
        As[aCol + 0][aRow] = a4.x;
        As[aCol + 1][aRow] = a4.y;
        As[aCol + 2][aRow] = a4.z;
        As[aCol + 3][aRow] = a4.w;
        *(float4*)&Bs[bRow][bCol] = b4;
        __syncthreads();
        #pragma unroll
        for (int kk = 0; kk < BKg; kk++) {
            float ar[8], br[8];
            *(float4*)&ar[0] = *(const float4*)&As[kk][ty * 8];
            *(float4*)&ar[4] = *(const float4*)&As[kk][ty * 8 + 4];
            *(float4*)&br[0] = *(const float4*)&Bs[kk][tx * 8];
            *(float4*)&br[4] = *(const float4*)&Bs[kk][tx * 8 + 4];
            #pragma unroll
            for (int i = 0; i < 8; i++)
                #pragma unroll
                for (int j = 0; j < 8; j++)
                    acc[i][j] = fmaf(ar[i], br[j], acc[i][j]);
        }
        __syncthreads();
    }

    #pragma unroll
    for (int i = 0; i < 8; i++) {
        int row = bm + ty * 8 + i;
        long orow;
        if (EPI == 2) {
            int b  = row >> 12;
            int wi = (row >> 9) & 7, wj = (row >> 6) & 7;
            int pi = (row >> 3) & 7, pj = row & 7;
            int h = (wi * 8 + pi + 4) & 63;   // scatter: final[(sh+4)%64]=win[sh]
            int w = (wj * 8 + pj + 4) & 63;
            orow = (long)b * 4096 + h * 64 + w;
        } else {
            orow = row;
        }
        #pragma unroll
        for (int j = 0; j < 8; j += 4) {
            int col = bn + tx * 8 + j;
            float4 v;
            v.x = acc[i][j + 0] + bias[col + 0];
            v.y = acc[i][j + 1] + bias[col + 1];
            v.z = acc[i][j + 2] + bias[col + 2];
            v.w = acc[i][j + 3] + bias[col + 3];
            if (EPI == 1) {
                v.x = 0.5f * v.x * (1.f + erff(v.x * 0.70710678118654752f));
                v.y = 0.5f * v.y * (1.f + erff(v.y * 0.70710678118654752f));
                v.z = 0.5f * v.z * (1.f + erff(v.z * 0.70710678118654752f));
                v.w = 0.5f * v.w * (1.f + erff(v.w * 0.70710678118654752f));
            }
            if (EPI == 2 || EPI == 3) {
                float4 rr = *(const float4*)(R + orow * N + col);
                v.x += rr.x; v.y += rr.y; v.z += rr.z; v.w += rr.w;
            }
            *(float4*)(C + orow * N + col) = v;
        }
    }
}

// ---------------------------------------------------------------------------
// Fused windowed attention: one block per (window, head).
// n=64 positions, hd=32.  Computes S=QK^T*scale + rel-pos bias + shift mask,
// row softmax, O = P V, all in SMEM.  Bias / mask computed on the fly.
// ---------------------------------------------------------------------------
__device__ __forceinline__ int bandf(int z) { return z < 56 ? 0 : (z < 60 ? 1 : 2); }

__global__ __launch_bounds__(256) void attn_kernel(
    const float* __restrict__ Q, const float* __restrict__ K,
    const float* __restrict__ V, const float* __restrict__ bt,
    float* __restrict__ O)
{
    __shared__ float Qs[64][33];
    __shared__ float Ks[64][33];
    __shared__ float Vs[64][33];
    __shared__ float Ps[64][65];

    int win  = blockIdx.x;
    int head = blockIdx.y;
    int t = threadIdx.x;
    long base = (long)win * 64 * C_DIM + head * 32;

    #pragma unroll
    for (int i = 0; i < 2; i++) {
        int idx = t + i * 256;          // 0..511 float4 slots (64 rows x 8)
        int row = idx >> 3, c4 = (idx & 7) * 4;
        float4 q4 = *(const float4*)(Q + base + (long)row * C_DIM + c4);
        float4 k4 = *(const float4*)(K + base + (long)row * C_DIM + c4);
        float4 v4 = *(const float4*)(V + base + (long)row * C_DIM + c4);
        Qs[row][c4] = q4.x; Qs[row][c4+1] = q4.y; Qs[row][c4+2] = q4.z; Qs[row][c4+3] = q4.w;
        Ks[row][c4] = k4.x; Ks[row][c4+1] = k4.y; Ks[row][c4+2] = k4.z; Ks[row][c4+3] = k4.w;
        Vs[row][c4] = v4.x; Vs[row][c4+1] = v4.y; Vs[row][c4+2] = v4.z; Vs[row][c4+3] = v4.w;
    }
    __syncthreads();

    int row = t >> 2, l = t & 3;        // quad of 4 threads per query row
    float qreg[32];
    #pragma unroll
    for (int kk = 0; kk < 32; kk++) qreg[kk] = Qs[row][kk];

    int yi = row >> 3, xi = row & 7;
    int w_in_b = win & 63;
    int wwi = w_in_b >> 3, wwj = w_in_b & 7;
    bool edge = (wwi == 7) || (wwj == 7);
    int id_i = 0;
    if (edge) id_i = bandf(wwi * 8 + yi) * 3 + bandf(wwj * 8 + xi);

    const float scale = 0.17677669529663687f;   // 32^-0.5
    float sreg[16];
    float mx = -1e30f;
    #pragma unroll
    for (int c = 0; c < 16; c++) {
        int col = c * 4 + l;            // stride-4 cols -> conflict-free Ks reads
        float s = 0.f;
        #pragma unroll
        for (int kk = 0; kk < 32; kk++) s = fmaf(qreg[kk], Ks[col][kk], s);
        s *= scale;
        int yj = col >> 3, xj = col & 7;
        s += bt[((yi - yj + 7) * 15 + (xi - xj + 7)) * 8 + head];
        if (edge) {
            int id_j = bandf(wwi * 8 + yj) * 3 + bandf(wwj * 8 + xj);
            if (id_i != id_j) s -= 100.f;
        }
        sreg[c] = s;
        mx = fmaxf(mx, s);
    }
    mx = fmaxf(mx, __shfl_xor_sync(0xffffffffu, mx, 1));
    mx = fmaxf(mx, __shfl_xor_sync(0xffffffffu, mx, 2));

    float sum = 0.f;
    #pragma unroll
    for (int c = 0; c < 16; c++) {
        float p = expf(sreg[c] - mx);
        sum += p;
        Ps[row][c * 4 + l] = p;
    }
    sum += __shfl_xor_sync(0xffffffffu, sum, 1);
    sum += __shfl_xor_sync(0xffffffffu, sum, 2);
    float rs = 1.f / sum;
    __syncthreads();

    float o[8];
    #pragma unroll
    for (int d = 0; d < 8; d++) o[d] = 0.f;
    #pragma unroll
    for (int col = 0; col < 64; col++) {
        float p = Ps[row][col];
        #pragma unroll
        for (int d = 0; d < 8; d++)
            o[d] = fmaf(p, Vs[col][l * 8 + d], o[d]);
    }
    float* op = O + base + (long)row * C_DIM + l * 8;
    float4 o0, o1;
    o0.x = o[0]*rs; o0.y = o[1]*rs; o0.z = o[2]*rs; o0.w = o[3]*rs;
    o1.x = o[4]*rs; o1.y = o[5]*rs; o1.z = o[6]*rs; o1.w = o[7]*rs;
    *(float4*)(op)     = o0;
    *(float4*)(op + 4) = o1;
}

// ---------------------------------------------------------------------------
// Launch
// ---------------------------------------------------------------------------
extern "C" void kernel_launch(void* const* d_in, const int* in_sizes, int n_in,
                              void* d_out, int out_size)
{
    const float* hidden = (const float*)d_in[0];
    const float* ln1_g  = (const float*)d_in[1];
    const float* ln1_b  = (const float*)d_in[2];
    const float* wq     = (const float*)d_in[3];
    const float* bq     = (const float*)d_in[4];
    const float* wk     = (const float*)d_in[5];
    const float* bk     = (const float*)d_in[6];
    const float* wv     = (const float*)d_in[7];
    const float* bv     = (const float*)d_in[8];
    const float* bt     = (const float*)d_in[9];
    const float* wo     = (const float*)d_in[10];
    const float* bo     = (const float*)d_in[11];
    const float* ln2_g  = (const float*)d_in[12];
    const float* ln2_b  = (const float*)d_in[13];
    const float* w1     = (const float*)d_in[14];
    const float* b1     = (const float*)d_in[15];
    const float* w2     = (const float*)d_in[16];
    const float* b2     = (const float*)d_in[17];
    float* out = (float*)d_out;

    float *p_xw, *p_q, *p_k, *p_v, *p_att, *p_hs, *p_y, *p_mid;
    cudaGetSymbolAddress((void**)&p_xw,  g_xw);
    cudaGetSymbolAddress((void**)&p_q,   g_q);
    cudaGetSymbolAddress((void**)&p_k,   g_k);
    cudaGetSymbolAddress((void**)&p_v,   g_v);
    cudaGetSymbolAddress((void**)&p_att, g_att);
    cudaGetSymbolAddress((void**)&p_hs,  g_hs);
    cudaGetSymbolAddress((void**)&p_y,   g_y);
    cudaGetSymbolAddress((void**)&p_mid, g_mid);

    dim3 blk(256);

    // 1. LN1 + cyclic shift + window partition
    ln_kernel<<<M_TOK, blk>>>(hidden, ln1_g, ln1_b, p_xw, 1);

    // 2. Q, K, V projections
    dim3 g256(C_DIM / BNg, M_TOK / BMg);   // (2, 1024)
    sgemm_kernel<0><<<g256, blk>>>(p_xw, wq, bq, nullptr, p_q, M_TOK, C_DIM, C_DIM);
    sgemm_kernel<0><<<g256, blk>>>(p_xw, wk, bk, nullptr, p_k, M_TOK, C_DIM, C_DIM);
    sgemm_kernel<0><<<g256, blk>>>(p_xw, wv, bv, nullptr, p_v, M_TOK, C_DIM, C_DIM);

    // 3. fused windowed attention (2048 windows x 8 heads)
    attn_kernel<<<dim3(2048, 8), blk>>>(p_q, p_k, p_v, bt, p_att);

    // 4. output projection + window reverse + roll + residual -> hs
    sgemm_kernel<2><<<g256, blk>>>(p_att, wo, bo, hidden, p_hs, M_TOK, C_DIM, C_DIM);

    // 5. LN2
    ln_kernel<<<M_TOK, blk>>>(p_hs, ln2_g, ln2_b, p_y, 0);

    // 6. MLP fc1 + exact GELU
    dim3 g1024(DFF / BNg, M_TOK / BMg);    // (8, 1024)
    sgemm_kernel<1><<<g1024, blk>>>(p_y, w1, b1, nullptr, p_mid, M_TOK, DFF, C_DIM);

    // 7. MLP fc2 + residual -> out
    sgemm_kernel<3><<<g256, blk>>>(p_mid, w2, b2, p_hs, out, M_TOK, C_DIM, DFF);
}

// round 3
// speedup vs baseline: 2.1887x; 2.1887x over previous
#include <cuda_runtime.h>
#include <math.h>
#include <stdint.h>

// ---------------------------------------------------------------------------
// Problem constants: B=32, H=W=64, C=256, NH=8, hd=32, WS=8, SS=4, IM=4
// Tokens M = 32*64*64 = 131072.  d_ff = 1024.
// ---------------------------------------------------------------------------
#define M_TOK   131072
#define C_DIM   256
#define DFF     1024

// Scratch (device globals; no allocation at runtime)
__device__ float g_xw  [M_TOK * C_DIM];
__device__ float g_q   [M_TOK * C_DIM];
__device__ float g_k   [M_TOK * C_DIM];
__device__ float g_v   [M_TOK * C_DIM];
__device__ float g_att [M_TOK * C_DIM];
__device__ float g_hs  [M_TOK * C_DIM];
__device__ float g_y   [M_TOK * C_DIM];
__device__ float g_mid [M_TOK * DFF];

// ---------------------------------------------------------------------------
// cp.async helpers
// ---------------------------------------------------------------------------
__device__ __forceinline__ void cp_async16(void* smem, const void* gmem) {
    uint32_t s = (uint32_t)__cvta_generic_to_shared(smem);
    asm volatile("cp.async.cg.shared.global [%0], [%1], 16;\n" :: "r"(s), "l"(gmem));
}
__device__ __forceinline__ void cp_commit() {
    asm volatile("cp.async.commit_group;\n");
}
template<int N>
__device__ __forceinline__ void cp_wait() {
    asm volatile("cp.async.wait_group %0;\n" :: "n"(N));
}

// ---------------------------------------------------------------------------
// LayerNorm kernel (gather=1: inverse roll+window-partition read mapping)
// ---------------------------------------------------------------------------
__global__ __launch_bounds__(256) void ln_kernel(
    const float* __restrict__ x, const float* __restrict__ g,
    const float* __restrict__ bb, float* __restrict__ out, int gather)
{
    int r = blockIdx.x;
    int c = threadIdx.x;
    long src;
    if (gather) {
        int b  = r >> 12;
        int wi = (r >> 9) & 7, wj = (r >> 6) & 7;
        int pi = (r >> 3) & 7, pj = r & 7;
        int h = (wi * 8 + pi + 4) & 63;
        int w = (wj * 8 + pj + 4) & 63;
        src = (long)b * 4096 + h * 64 + w;
    } else {
        src = r;
    }
    float v = x[src * C_DIM + c];
    float s = v, s2 = v * v;
    #pragma unroll
    for (int o = 16; o > 0; o >>= 1) {
        s  += __shfl_xor_sync(0xffffffffu, s, o);
        s2 += __shfl_xor_sync(0xffffffffu, s2, o);
    }
    __shared__ float sh[8], sh2[8];
    int warp = c >> 5, lane = c & 31;
    if (lane == 0) { sh[warp] = s; sh2[warp] = s2; }
    __syncthreads();
    float ts = 0.f, ts2 = 0.f;
    #pragma unroll
    for (int wwi = 0; wwi < 8; wwi++) { ts += sh[wwi]; ts2 += sh2[wwi]; }
    float mean = ts * (1.f / 256.f);
    float var  = ts2 * (1.f / 256.f) - mean * mean;
    float rstd = rsqrtf(var + 1e-5f);
    out[(long)r * C_DIM + c] = (v - mean) * rstd * g[c] + bb[c];
}

// ---------------------------------------------------------------------------
// TF32 tensor-core GEMM: C = epi(A[MxK] @ B[KxN] + bias)
// EPI: 0 plain, 1 GELU, 2 scatter(window-reverse+roll)+residual, 3 residual.
// 128x128 tile, BK=16, 256 threads (8 warps, 32x64 warp tiles),
// mma.sync.m16n8k8.tf32, cp.async double buffering.
// ---------------------------------------------------------------------------
#define ASTRIDE 20     // 16 + 4 pad: conflict-free A fragment LDS
#define BSTRIDE 132    // 128 + 4 pad

__device__ __forceinline__ void mma_tf32(float d[4], const uint32_t a[4], const uint32_t b[2]) {
    asm volatile(
        "mma.sync.aligned.m16n8k8.row.col.f32.tf32.tf32.f32 "
        "{%0,%1,%2,%3}, {%4,%5,%6,%7}, {%8,%9}, {%0,%1,%2,%3};\n"
        : "+f"(d[0]), "+f"(d[1]), "+f"(d[2]), "+f"(d[3])
        : "r"(a[0]), "r"(a[1]), "r"(a[2]), "r"(a[3]), "r"(b[0]), "r"(b[1]));
}

template<int EPI>
__global__ __launch_bounds__(256) void tf32gemm(
    const float* __restrict__ A, const float* __restrict__ B,
    const float* __restrict__ bias, const float* __restrict__ R,
    float* __restrict__ C, int M, int N, int K)
{
    __shared__ float As[2][128 * ASTRIDE];
    __shared__ float Bs[2][16 * BSTRIDE];

    int tid  = threadIdx.x;
    int lane = tid & 31, warp = tid >> 5;
    int wm = warp >> 1, wn = warp & 1;          // 4 (m) x 2 (n) warp grid
    int bm = blockIdx.y * 128, bn = blockIdx.x * 128;
    int gid = lane >> 2, tig = lane & 3;

    float acc[2][8][4];
    #pragma unroll
    for (int mt = 0; mt < 2; mt++)
        #pragma unroll
        for (int nt = 0; nt < 8; nt++)
            #pragma unroll
            for (int i = 0; i < 4; i++) acc[mt][nt][i] = 0.f;

    // A tile: 128 rows x 16 cols = 512 float4 segs; B tile: 16 x 128 = 512 segs
    int aR[2], aC[2], bR[2], bC[2];
    #pragma unroll
    for (int i = 0; i < 2; i++) {
        int s = tid + i * 256;
        aR[i] = s >> 2;  aC[i] = (s & 3) * 4;
        bR[i] = s >> 5;  bC[i] = (s & 31) * 4;
    }

    int KT = K >> 4;
    // prologue
    #pragma unroll
    for (int i = 0; i < 2; i++) {
        cp_async16(&As[0][aR[i] * ASTRIDE + aC[i]], A + (long)(bm + aR[i]) * K + aC[i]);
        cp_async16(&Bs[0][bR[i] * BSTRIDE + bC[i]], B + (long)bR[i] * N + bn + bC[i]);
    }
    cp_commit();

    int buf = 0;
    for (int kt = 0; kt < KT; kt++) {
        if (kt + 1 < KT) {
            int kb = (kt + 1) << 4;
            #pragma unroll
            for (int i = 0; i < 2; i++) {
                cp_async16(&As[buf ^ 1][aR[i] * ASTRIDE + aC[i]],
                           A + (long)(bm + aR[i]) * K + kb + aC[i]);
                cp_async16(&Bs[buf ^ 1][bR[i] * BSTRIDE + bC[i]],
                           B + (long)(kb + bR[i]) * N + bn + bC[i]);
            }
            cp_commit();
            cp_wait<1>();
        } else {
            cp_wait<0>();
        }
        __syncthreads();

        const float* as = As[buf];
        const float* bs = Bs[buf];
        #pragma unroll
        for (int ks = 0; ks < 2; ks++) {
            uint32_t af[2][4], bfr[8][2];
            #pragma unroll
            for (int mt = 0; mt < 2; mt++) {
                int r0 = wm * 32 + mt * 16 + gid;
                int c0 = ks * 8 + tig;
                af[mt][0] = __float_as_uint(as[r0 * ASTRIDE + c0]);
                af[mt][1] = __float_as_uint(as[(r0 + 8) * ASTRIDE + c0]);
                af[mt][2] = __float_as_uint(as[r0 * ASTRIDE + c0 + 4]);
                af[mt][3] = __float_as_uint(as[(r0 + 8) * ASTRIDE + c0 + 4]);
            }
            #pragma unroll
            for (int nt = 0; nt < 8; nt++) {
                int rr = ks * 8 + tig;
                int cc = wn * 64 + nt * 8 + gid;
                bfr[nt][0] = __float_as_uint(bs[rr * BSTRIDE + cc]);
                bfr[nt][1] = __float_as_uint(bs[(rr + 4) * BSTRIDE + cc]);
            }
            #pragma unroll
            for (int mt = 0; mt < 2; mt++)
                #pragma unroll
                for (int nt = 0; nt < 8; nt++)
                    mma_tf32(acc[mt][nt], af[mt], bfr[nt]);
        }
        __syncthreads();
        buf ^= 1;
    }

    // epilogue
    #pragma unroll
    for (int mt = 0; mt < 2; mt++) {
        #pragma unroll
        for (int half = 0; half < 2; half++) {
            int row = bm + wm * 32 + mt * 16 + half * 8 + gid;
            long orow;
            if (EPI == 2) {
                int b  = row >> 12;
                int wi = (row >> 9) & 7, wj = (row >> 6) & 7;
                int pi = (row >> 3) & 7, pj = row & 7;
                int h = (wi * 8 + pi + 4) & 63;
                int w = (wj * 8 + pj + 4) & 63;
                orow = (long)b * 4096 + h * 64 + w;
            } else {
                orow = row;
            }
            #pragma unroll
            for (int nt = 0; nt < 8; nt++) {
                int col = bn + wn * 64 + nt * 8 + 2 * tig;
                float v0 = acc[mt][nt][half * 2 + 0] + bias[col];
                float v1 = acc[mt][nt][half * 2 + 1] + bias[col + 1];
                if (EPI == 1) {
                    v0 = 0.5f * v0 * (1.f + erff(v0 * 0.70710678118654752f));
                    v1 = 0.5f * v1 * (1.f + erff(v1 * 0.70710678118654752f));
                }
                if (EPI == 2 || EPI == 3) {
                    float2 rr = *(const float2*)(R + orow * N + col);
                    v0 += rr.x; v1 += rr.y;
                }
                float2 o; o.x = v0; o.y = v1;
                *(float2*)(C + orow * N + col) = o;
            }
        }
    }
}

// ---------------------------------------------------------------------------
// Fused windowed attention (fp32 SIMT), one block per (window, head)
// ---------------------------------------------------------------------------
__device__ __forceinline__ int bandf(int z) { return z < 56 ? 0 : (z < 60 ? 1 : 2); }

__global__ __launch_bounds__(256) void attn_kernel(
    const float* __restrict__ Q, const float* __restrict__ K,
    const float* __restrict__ V, const float* __restrict__ bt,
    float* __restrict__ O)
{
    __shared__ float Qs[64][33];
    __shared__ float Ks[64][33];
    __shared__ float Vs[64][33];
    __shared__ float Ps[64][65];

    int win  = blockIdx.x;
    int head = blockIdx.y;
    int t = threadIdx.x;
    long base = (long)win * 64 * C_DIM + head * 32;

    #pragma unroll
    for (int i = 0; i < 2; i++) {
        int idx = t + i * 256;
        int row = idx >> 3, c4 = (idx & 7) * 4;
        float4 q4 = *(const float4*)(Q + base + (long)row * C_DIM + c4);
        float4 k4 = *(const float4*)(K + base + (long)row * C_DIM + c4);
        float4 v4 = *(const float4*)(V + base + (long)row * C_DIM + c4);
        Qs[row][c4] = q4.x; Qs[row][c4+1] = q4.y; Qs[row][c4+2] = q4.z; Qs[row][c4+3] = q4.w;
        Ks[row][c4] = k4.x; Ks[row][c4+1] = k4.y; Ks[row][c4+2] = k4.z; Ks[row][c4+3] = k4.w;
        Vs[row][c4] = v4.x; Vs[row][c4+1] = v4.y; Vs[row][c4+2] = v4.z; Vs[row][c4+3] = v4.w;
    }
    __syncthreads();

    int row = t >> 2, l = t & 3;
    float qreg[32];
    #pragma unroll
    for (int kk = 0; kk < 32; kk++) qreg[kk] = Qs[row][kk];

    int yi = row >> 3, xi = row & 7;
    int w_in_b = win & 63;
    int wwi = w_in_b >> 3, wwj = w_in_b & 7;
    bool edge = (wwi == 7) || (wwj == 7);
    int id_i = 0;
    if (edge) id_i = bandf(wwi * 8 + yi) * 3 + bandf(wwj * 8 + xi);

    const float scale = 0.17677669529663687f;
    float sreg[16];
    float mx = -1e30f;
    #pragma unroll
    for (int c = 0; c < 16; c++) {
        int col = c * 4 + l;
        float s = 0.f;
        #pragma unroll
        for (int kk = 0; kk < 32; kk++) s = fmaf(qreg[kk], Ks[col][kk], s);
        s *= scale;
        int yj = col >> 3, xj = col & 7;
        s += bt[((yi - yj + 7) * 15 + (xi - xj + 7)) * 8 + head];
        if (edge) {
            int id_j = bandf(wwi * 8 + yj) * 3 + bandf(wwj * 8 + xj);
            if (id_i != id_j) s -= 100.f;
        }
        sreg[c] = s;
        mx = fmaxf(mx, s);
    }
    mx = fmaxf(mx, __shfl_xor_sync(0xffffffffu, mx, 1));
    mx = fmaxf(mx, __shfl_xor_sync(0xffffffffu, mx, 2));

    float sum = 0.f;
    #pragma unroll
    for (int c = 0; c < 16; c++) {
        float p = expf(sreg[c] - mx);
        sum += p;
        Ps[row][c * 4 + l] = p;
    }
    sum += __shfl_xor_sync(0xffffffffu, sum, 1);
    sum += __shfl_xor_sync(0xffffffffu, sum, 2);
    float rs = 1.f / sum;
    __syncthreads();

    float o[8];
    #pragma unroll
    for (int d = 0; d < 8; d++) o[d] = 0.f;
    #pragma unroll
    for (int col = 0; col < 64; col++) {
        float p = Ps[row][col];
        #pragma unroll
        for (int d = 0; d < 8; d++)
            o[d] = fmaf(p, Vs[col][l * 8 + d], o[d]);
    }
    float* op = O + base + (long)row * C_DIM + l * 8;
    float4 o0, o1;
    o0.x = o[0]*rs; o0.y = o[1]*rs; o0.z = o[2]*rs; o0.w = o[3]*rs;
    o1.x = o[4]*rs; o1.y = o[5]*rs; o1.z = o[6]*rs; o1.w = o[7]*rs;
    *(float4*)(op)     = o0;
    *(float4*)(op + 4) = o1;
}

// ---------------------------------------------------------------------------
// Launch
// ---------------------------------------------------------------------------
extern "C" void kernel_launch(void* const* d_in, const int* in_sizes, int n_in,
                              void* d_out, int out_size)
{
    const float* hidden = (const float*)d_in[0];
    const float* ln1_g  = (const float*)d_in[1];
    const float* ln1_b  = (const float*)d_in[2];
    const float* wq     = (const float*)d_in[3];
    const float* bq     = (const float*)d_in[4];
    const float* wk     = (const float*)d_in[5];
    const float* bk     = (const float*)d_in[6];
    const float* wv     = (const float*)d_in[7];
    const float* bv     = (const float*)d_in[8];
    const float* bt     = (const float*)d_in[9];
    const float* wo     = (const float*)d_in[10];
    const float* bo     = (const float*)d_in[11];
    const float* ln2_g  = (const float*)d_in[12];
    const float* ln2_b  = (const float*)d_in[13];
    const float* w1     = (const float*)d_in[14];
    const float* b1     = (const float*)d_in[15];
    const float* w2     = (const float*)d_in[16];
    const float* b2     = (const float*)d_in[17];
    float* out = (float*)d_out;

    float *p_xw, *p_q, *p_k, *p_v, *p_att, *p_hs, *p_y, *p_mid;
    cudaGetSymbolAddress((void**)&p_xw,  g_xw);
    cudaGetSymbolAddress((void**)&p_q,   g_q);
    cudaGetSymbolAddress((void**)&p_k,   g_k);
    cudaGetSymbolAddress((void**)&p_v,   g_v);
    cudaGetSymbolAddress((void**)&p_att, g_att);
    cudaGetSymbolAddress((void**)&p_hs,  g_hs);
    cudaGetSymbolAddress((void**)&p_y,   g_y);
    cudaGetSymbolAddress((void**)&p_mid, g_mid);

    dim3 blk(256);

    // 1. LN1 + cyclic shift + window partition
    ln_kernel<<<M_TOK, blk>>>(hidden, ln1_g, ln1_b, p_xw, 1);

    // 2. Q, K, V projections (tf32 tensor cores)
    dim3 g256(C_DIM / 128, M_TOK / 128);
    tf32gemm<0><<<g256, blk>>>(p_xw, wq, bq, nullptr, p_q, M_TOK, C_DIM, C_DIM);
    tf32gemm<0><<<g256, blk>>>(p_xw, wk, bk, nullptr, p_k, M_TOK, C_DIM, C_DIM);
    tf32gemm<0><<<g256, blk>>>(p_xw, wv, bv, nullptr, p_v, M_TOK, C_DIM, C_DIM);

    // 3. fused windowed attention
    attn_kernel<<<dim3(2048, 8), blk>>>(p_q, p_k, p_v, bt, p_att);

    // 4. output projection + window reverse + roll + residual -> hs
    tf32gemm<2><<<g256, blk>>>(p_att, wo, bo, hidden, p_hs, M_TOK, C_DIM, C_DIM);

    // 5. LN2
    ln_kernel<<<M_TOK, blk>>>(p_hs, ln2_g, ln2_b, p_y, 0);

    // 6. MLP fc1 + exact GELU
    dim3 g1024(DFF / 128, M_TOK / 128);
    tf32gemm<1><<<g1024, blk>>>(p_y, w1, b1, nullptr, p_mid, M_TOK, DFF, C_DIM);

    // 7. MLP fc2 + residual -> out
    tf32gemm<3><<<g256, blk>>>(p_mid, w2, b2, p_hs, out, M_TOK, C_DIM, DFF);
}

// round 4
// speedup vs baseline: 2.5320x; 1.1568x over previous
#include <cuda_runtime.h>
#include <math.h>
#include <stdint.h>

// ---------------------------------------------------------------------------
// Problem constants: B=32, H=W=64, C=256, NH=8, hd=32, WS=8, SS=4, IM=4
// ---------------------------------------------------------------------------
#define M_TOK   131072
#define C_DIM   256
#define DFF     1024

// Scratch (device globals; no allocation at runtime)
__device__ float g_xw   [M_TOK * C_DIM];
__device__ float g_qkv  [M_TOK * 768];
__device__ float g_att  [M_TOK * C_DIM];
__device__ float g_hs   [M_TOK * C_DIM];
__device__ float g_y    [M_TOK * C_DIM];
__device__ float g_mid  [M_TOK * DFF];
__device__ float g_wqkv [C_DIM * 768];
__device__ float g_bqkv [768];

// ---------------------------------------------------------------------------
// cp.async helpers
// ---------------------------------------------------------------------------
__device__ __forceinline__ void cp_async16(void* smem, const void* gmem) {
    uint32_t s = (uint32_t)__cvta_generic_to_shared(smem);
    asm volatile("cp.async.cg.shared.global [%0], [%1], 16;\n" :: "r"(s), "l"(gmem));
}
__device__ __forceinline__ void cp_commit() {
    asm volatile("cp.async.commit_group;\n");
}
template<int N>
__device__ __forceinline__ void cp_wait() {
    asm volatile("cp.async.wait_group %0;\n" :: "n"(N));
}

// ---------------------------------------------------------------------------
// Pack wq|wk|wv -> [256,768], bq|bk|bv -> [768]
// ---------------------------------------------------------------------------
__global__ __launch_bounds__(256) void pack_qkv(
    const float* __restrict__ wq, const float* __restrict__ wk,
    const float* __restrict__ wv, const float* __restrict__ bq,
    const float* __restrict__ bk, const float* __restrict__ bv,
    float* __restrict__ wdst, float* __restrict__ bdst)
{
    int idx = blockIdx.x * 256 + threadIdx.x;       // 0 .. 196607
    int k = idx / 768, n = idx % 768;
    float v = (n < 256) ? wq[k * 256 + n]
            : (n < 512) ? wk[k * 256 + n - 256]
                        : wv[k * 256 + n - 512];
    wdst[idx] = v;
    if (idx < 768)
        bdst[idx] = (idx < 256) ? bq[idx] : (idx < 512) ? bk[idx - 256] : bv[idx - 512];
}

// ---------------------------------------------------------------------------
// LayerNorm: warp-per-token, 8 tokens/block, float4 I/O.
// gather=1: read through inverse (roll -4,-4 + window partition) mapping.
// ---------------------------------------------------------------------------
__global__ __launch_bounds__(256) void ln_kernel(
    const float* __restrict__ x, const float* __restrict__ g,
    const float* __restrict__ bb, float* __restrict__ out, int gather)
{
    int warp = threadIdx.x >> 5, lane = threadIdx.x & 31;
    int r = blockIdx.x * 8 + warp;
    long src;
    if (gather) {
        int b  = r >> 12;
        int wi = (r >> 9) & 7, wj = (r >> 6) & 7;
        int pi = (r >> 3) & 7, pj = r & 7;
        int h = (wi * 8 + pi + 4) & 63;
        int w = (wj * 8 + pj + 4) & 63;
        src = (long)b * 4096 + h * 64 + w;
    } else {
        src = r;
    }
    const float4* xp = (const float4*)(x + src * C_DIM);
    float4 v0 = xp[lane * 2], v1 = xp[lane * 2 + 1];
    float s  = v0.x + v0.y + v0.z + v0.w + v1.x + v1.y + v1.z + v1.w;
    float s2 = v0.x*v0.x + v0.y*v0.y + v0.z*v0.z + v0.w*v0.w
             + v1.x*v1.x + v1.y*v1.y + v1.z*v1.z + v1.w*v1.w;
    #pragma unroll
    for (int o = 16; o > 0; o >>= 1) {
        s  += __shfl_xor_sync(0xffffffffu, s, o);
        s2 += __shfl_xor_sync(0xffffffffu, s2, o);
    }
    float mean = s * (1.f / 256.f);
    float var  = s2 * (1.f / 256.f) - mean * mean;
    float rstd = rsqrtf(var + 1e-5f);
    const float4* gp = (const float4*)(g  + lane * 8);
    const float4* bp = (const float4*)(bb + lane * 8);
    float4 g0 = gp[0], g1 = gp[1], b0 = bp[0], b1 = bp[1];
    float4 o0, o1;
    o0.x = (v0.x - mean) * rstd * g0.x + b0.x;
    o0.y = (v0.y - mean) * rstd * g0.y + b0.y;
    o0.z = (v0.z - mean) * rstd * g0.z + b0.z;
    o0.w = (v0.w - mean) * rstd * g0.w + b0.w;
    o1.x = (v1.x - mean) * rstd * g1.x + b1.x;
    o1.y = (v1.y - mean) * rstd * g1.y + b1.y;
    o1.z = (v1.z - mean) * rstd * g1.z + b1.z;
    o1.w = (v1.w - mean) * rstd * g1.w + b1.w;
    float4* op = (float4*)(out + (long)r * C_DIM + lane * 8);
    op[0] = o0; op[1] = o1;
}

// ---------------------------------------------------------------------------
// TF32 tensor-core GEMM: C = epi(A[MxK] @ B[KxN] + bias)
// EPI: 0 plain, 1 GELU, 2 scatter(window-reverse+roll)+residual, 3 residual.
// Block 128x256, BK=16, 3-stage cp.async, 8 warps (2m x 4n), warp tile 64x64.
// Conflict-free fragment strides: ASTR=20 (mod32=20), BSTR=264 (mod32=8).
// ---------------------------------------------------------------------------
#define NSTG 3
#define BM   128
#define BN   256
#define ASTR 20
#define BSTR 264
#define A_STAGE (BM * ASTR)    // 2560 floats
#define B_STAGE (16 * BSTR)    // 4224 floats
#define SMEM_SZ ((NSTG * (A_STAGE + B_STAGE)) * 4)   // 81408 bytes

__device__ __forceinline__ void mma_tf32(float d[4], const uint32_t a[4], const uint32_t b[2]) {
    asm volatile(
        "mma.sync.aligned.m16n8k8.row.col.f32.tf32.tf32.f32 "
        "{%0,%1,%2,%3}, {%4,%5,%6,%7}, {%8,%9}, {%0,%1,%2,%3};\n"
        : "+f"(d[0]), "+f"(d[1]), "+f"(d[2]), "+f"(d[3])
        : "r"(a[0]), "r"(a[1]), "r"(a[2]), "r"(a[3]), "r"(b[0]), "r"(b[1]));
}

template<int EPI>
__global__ __launch_bounds__(256, 1) void tf32gemm(
    const float* __restrict__ A, const float* __restrict__ B,
    const float* __restrict__ bias, const float* __restrict__ R,
    float* __restrict__ C, int M, int N, int K)
{
    extern __shared__ float sm[];
    float* Asm = sm;
    float* Bsm = sm + NSTG * A_STAGE;

    int tid  = threadIdx.x;
    int lane = tid & 31, warp = tid >> 5;
    int wm = warp >> 2, wn = warp & 3;      // 2 (m) x 4 (n)
    int bm = blockIdx.y * BM, bn = blockIdx.x * BN;
    int gid = lane >> 2, tig = lane & 3;

    float acc[4][8][4];
    #pragma unroll
    for (int mt = 0; mt < 4; mt++)
        #pragma unroll
        for (int nt = 0; nt < 8; nt++)
            #pragma unroll
            for (int i = 0; i < 4; i++) acc[mt][nt][i] = 0.f;

    // A: 128x16 = 512 float4 segs (2/thread); B: 16x256 = 1024 segs (4/thread)
    int aR[2], aC[2], bR[4], bC[4];
    #pragma unroll
    for (int i = 0; i < 2; i++) {
        int s = tid + i * 256;
        aR[i] = s >> 2;  aC[i] = (s & 3) * 4;
    }
    #pragma unroll
    for (int i = 0; i < 4; i++) {
        int s = tid + i * 256;
        bR[i] = s >> 6;  bC[i] = (s & 63) * 4;
    }

    int KT = K >> 4;

    #pragma unroll
    for (int s = 0; s < NSTG - 1; s++) {
        int kb = s << 4;
        float* as = Asm + s * A_STAGE;
        float* bs = Bsm + s * B_STAGE;
        #pragma unroll
        for (int i = 0; i < 2; i++)
            cp_async16(&as[aR[i] * ASTR + aC[i]], A + (long)(bm + aR[i]) * K + kb + aC[i]);
        #pragma unroll
        for (int i = 0; i < 4; i++)
            cp_async16(&bs[bR[i] * BSTR + bC[i]], B + (long)(kb + bR[i]) * N + bn + bC[i]);
        cp_commit();
    }

    for (int kt = 0; kt < KT; kt++) {
        if (kt + NSTG - 1 < KT) cp_wait<NSTG - 2>(); else cp_wait<0>();
        __syncthreads();
        int stg = kt % NSTG;
        const float* as = Asm + stg * A_STAGE;
        const float* bs = Bsm + stg * B_STAGE;
        #pragma unroll
        for (int ks = 0; ks < 2; ks++) {
            uint32_t af[4][4], bf[8][2];
            #pragma unroll
            for (int mt = 0; mt < 4; mt++) {
                int r0 = wm * 64 + mt * 16 + gid;
                int c0 = ks * 8 + tig;
                af[mt][0] = __float_as_uint(as[r0 * ASTR + c0]);
                af[mt][1] = __float_as_uint(as[(r0 + 8) * ASTR + c0]);
                af[mt][2] = __float_as_uint(as[r0 * ASTR + c0 + 4]);
                af[mt][3] = __float_as_uint(as[(r0 + 8) * ASTR + c0 + 4]);
            }
            #pragma unroll
            for (int nt = 0; nt < 8; nt++) {
                int rr = ks * 8 + tig;
                int cc = wn * 64 + nt * 8 + gid;
                bf[nt][0] = __float_as_uint(bs[rr * BSTR + cc]);
                bf[nt][1] = __float_as_uint(bs[(rr + 4) * BSTR + cc]);
            }
            #pragma unroll
            for (int mt = 0; mt < 4; mt++)
                #pragma unroll
                for (int nt = 0; nt < 8; nt++)
                    mma_tf32(acc[mt][nt], af[mt], bf[nt]);
        }
        // Load stage kt+NSTG-1 into buffer (kt-1)%NSTG: all warps finished
        // computing that buffer before the __syncthreads above.
        if (kt + NSTG - 1 < KT) {
            int kn = kt + NSTG - 1;
            int kb = kn << 4;
            int ds = kn % NSTG;
            float* asn = Asm + ds * A_STAGE;
            float* bsn = Bsm + ds * B_STAGE;
            #pragma unroll
            for (int i = 0; i < 2; i++)
                cp_async16(&asn[aR[i] * ASTR + aC[i]], A + (long)(bm + aR[i]) * K + kb + aC[i]);
            #pragma unroll
            for (int i = 0; i < 4; i++)
                cp_async16(&bsn[bR[i] * BSTR + bC[i]], B + (long)(kb + bR[i]) * N + bn + bC[i]);
            cp_commit();
        }
    }

    // epilogue
    #pragma unroll
    for (int mt = 0; mt < 4; mt++) {
        #pragma unroll
        for (int half = 0; half < 2; half++) {
            int row = bm + wm * 64 + mt * 16 + half * 8 + gid;
            long orow;
            if (EPI == 2) {
                int b  = row >> 12;
                int wi = (row >> 9) & 7, wj = (row >> 6) & 7;
                int pi = (row >> 3) & 7, pj = row & 7;
                int h = (wi * 8 + pi + 4) & 63;
                int w = (wj * 8 + pj + 4) & 63;
                orow = (long)b * 4096 + h * 64 + w;
            } else {
                orow = row;
            }
            #pragma unroll
            for (int nt = 0; nt < 8; nt++) {
                int col = bn + wn * 64 + nt * 8 + 2 * tig;
                float v0 = acc[mt][nt][half * 2 + 0] + bias[col];
                float v1 = acc[mt][nt][half * 2 + 1] + bias[col + 1];
                if (EPI == 1) {
                    v0 = 0.5f * v0 * (1.f + erff(v0 * 0.70710678118654752f));
                    v1 = 0.5f * v1 * (1.f + erff(v1 * 0.70710678118654752f));
                }
                if (EPI == 2 || EPI == 3) {
                    float2 rr = *(const float2*)(R + orow * N + col);
                    v0 += rr.x; v1 += rr.y;
                }
                float2 o; o.x = v0; o.y = v1;
                *(float2*)(C + orow * N + col) = o;
            }
        }
    }
}

// ---------------------------------------------------------------------------
// Fused windowed attention: QKV fused buffer (stride 768), output stride 256.
// ---------------------------------------------------------------------------
__device__ __forceinline__ int bandf(int z) { return z < 56 ? 0 : (z < 60 ? 1 : 2); }

__global__ __launch_bounds__(256) void attn_kernel(
    const float* __restrict__ QKV, const float* __restrict__ bt,
    float* __restrict__ O)
{
    __shared__ float Qs[64][33];
    __shared__ float Ks[64][33];
    __shared__ float Vs[64][33];
    __shared__ float Ps[64][65];

    int win  = blockIdx.x;
    int head = blockIdx.y;
    int t = threadIdx.x;
    long base = (long)win * 64 * 768 + head * 32;

    #pragma unroll
    for (int i = 0; i < 2; i++) {
        int idx = t + i * 256;
        int row = idx >> 3, c4 = (idx & 7) * 4;
        const float* src = QKV + base + (long)row * 768 + c4;
        float4 q4 = *(const float4*)(src);
        float4 k4 = *(const float4*)(src + 256);
        float4 v4 = *(const float4*)(src + 512);
        Qs[row][c4] = q4.x; Qs[row][c4+1] = q4.y; Qs[row][c4+2] = q4.z; Qs[row][c4+3] = q4.w;
        Ks[row][c4] = k4.x; Ks[row][c4+1] = k4.y; Ks[row][c4+2] = k4.z; Ks[row][c4+3] = k4.w;
        Vs[row][c4] = v4.x; Vs[row][c4+1] = v4.y; Vs[row][c4+2] = v4.z; Vs[row][c4+3] = v4.w;
    }
    __syncthreads();

    int row = t >> 2, l = t & 3;
    float qreg[32];
    #pragma unroll
    for (int kk = 0; kk < 32; kk++) qreg[kk] = Qs[row][kk];

    int yi = row >> 3, xi = row & 7;
    int w_in_b = win & 63;
    int wwi = w_in_b >> 3, wwj = w_in_b & 7;
    bool edge = (wwi == 7) || (wwj == 7);
    int id_i = 0;
    if (edge) id_i = bandf(wwi * 8 + yi) * 3 + bandf(wwj * 8 + xi);

    const float scale = 0.17677669529663687f;
    float sreg[16];
    float mx = -1e30f;
    #pragma unroll
    for (int c = 0; c < 16; c++) {
        int col = c * 4 + l;
        float s = 0.f;
        #pragma unroll
        for (int kk = 0; kk < 32; kk++) s = fmaf(qreg[kk], Ks[col][kk], s);
        s *= scale;
        int yj = col >> 3, xj = col & 7;
        s += bt[((yi - yj + 7) * 15 + (xi - xj + 7)) * 8 + head];
        if (edge) {
            int id_j = bandf(wwi * 8 + yj) * 3 + bandf(wwj * 8 + xj);
            if (id_i != id_j) s -= 100.f;
        }
        sreg[c] = s;
        mx = fmaxf(mx, s);
    }
    mx = fmaxf(mx, __shfl_xor_sync(0xffffffffu, mx, 1));
    mx = fmaxf(mx, __shfl_xor_sync(0xffffffffu, mx, 2));

    float sum = 0.f;
    #pragma unroll
    for (int c = 0; c < 16; c++) {
        float p = expf(sreg[c] - mx);
        sum += p;
        Ps[row][c * 4 + l] = p;
    }
    sum += __shfl_xor_sync(0xffffffffu, sum, 1);
    sum += __shfl_xor_sync(0xffffffffu, sum, 2);
    float rs = 1.f / sum;
    __syncthreads();

    float o[8];
    #pragma unroll
    for (int d = 0; d < 8; d++) o[d] = 0.f;
    #pragma unroll
    for (int col = 0; col < 64; col++) {
        float p = Ps[row][col];
        #pragma unroll
        for (int d = 0; d < 8; d++)
            o[d] = fmaf(p, Vs[col][l * 8 + d], o[d]);
    }
    float* op = O + ((long)win * 64 + row) * C_DIM + head * 32 + l * 8;
    float4 o0, o1;
    o0.x = o[0]*rs; o0.y = o[1]*rs; o0.z = o[2]*rs; o0.w = o[3]*rs;
    o1.x = o[4]*rs; o1.y = o[5]*rs; o1.z = o[6]*rs; o1.w = o[7]*rs;
    *(float4*)(op)     = o0;
    *(float4*)(op + 4) = o1;
}

// ---------------------------------------------------------------------------
// Launch
// ---------------------------------------------------------------------------
extern "C" void kernel_launch(void* const* d_in, const int* in_sizes, int n_in,
                              void* d_out, int out_size)
{
    const float* hidden = (const float*)d_in[0];
    const float* ln1_g  = (const float*)d_in[1];
    const float* ln1_b  = (const float*)d_in[2];
    const float* wq     = (const float*)d_in[3];
    const float* bq     = (const float*)d_in[4];
    const float* wk     = (const float*)d_in[5];
    const float* bk     = (const float*)d_in[6];
    const float* wv     = (const float*)d_in[7];
    const float* bv     = (const float*)d_in[8];
    const float* bt     = (const float*)d_in[9];
    const float* wo     = (const float*)d_in[10];
    const float* bo     = (const float*)d_in[11];
    const float* ln2_g  = (const float*)d_in[12];
    const float* ln2_b  = (const float*)d_in[13];
    const float* w1     = (const float*)d_in[14];
    const float* b1     = (const float*)d_in[15];
    const float* w2     = (const float*)d_in[16];
    const float* b2     = (const float*)d_in[17];
    float* out = (float*)d_out;

    float *p_xw, *p_qkv, *p_att, *p_hs, *p_y, *p_mid, *p_wqkv, *p_bqkv;
    cudaGetSymbolAddress((void**)&p_xw,   g_xw);
    cudaGetSymbolAddress((void**)&p_qkv,  g_qkv);
    cudaGetSymbolAddress((void**)&p_att,  g_att);
    cudaGetSymbolAddress((void**)&p_hs,   g_hs);
    cudaGetSymbolAddress((void**)&p_y,    g_y);
    cudaGetSymbolAddress((void**)&p_mid,  g_mid);
    cudaGetSymbolAddress((void**)&p_wqkv, g_wqkv);
    cudaGetSymbolAddress((void**)&p_bqkv, g_bqkv);

    cudaFuncSetAttribute(tf32gemm<0>, cudaFuncAttributeMaxDynamicSharedMemorySize, SMEM_SZ);
    cudaFuncSetAttribute(tf32gemm<1>, cudaFuncAttributeMaxDynamicSharedMemorySize, SMEM_SZ);
    cudaFuncSetAttribute(tf32gemm<2>, cudaFuncAttributeMaxDynamicSharedMemorySize, SMEM_SZ);
    cudaFuncSetAttribute(tf32gemm<3>, cudaFuncAttributeMaxDynamicSharedMemorySize, SMEM_SZ);

    dim3 blk(256);

    // 0. pack QKV weights/bias
    pack_qkv<<<768, blk>>>(wq, wk, wv, bq, bk, bv, p_wqkv, p_bqkv);

    // 1. LN1 + cyclic shift + window partition
    ln_kernel<<<M_TOK / 8, blk>>>(hidden, ln1_g, ln1_b, p_xw, 1);

    // 2. fused QKV projection (N=768)
    tf32gemm<0><<<dim3(768 / BN, M_TOK / BM), blk, SMEM_SZ>>>(
        p_xw, p_wqkv, p_bqkv, nullptr, p_qkv, M_TOK, 768, C_DIM);

    // 3. fused windowed attention
    attn_kernel<<<dim3(2048, 8), blk>>>(p_qkv, bt, p_att);

    // 4. output projection + window reverse + roll + residual -> hs
    tf32gemm<2><<<dim3(C_DIM / BN, M_TOK / BM), blk, SMEM_SZ>>>(
        p_att, wo, bo, hidden, p_hs, M_TOK, C_DIM, C_DIM);

    // 5. LN2
    ln_kernel<<<M_TOK / 8, blk>>>(p_hs, ln2_g, ln2_b, p_y, 0);

    // 6. MLP fc1 + exact GELU
    tf32gemm<1><<<dim3(DFF / BN, M_TOK / BM), blk, SMEM_SZ>>>(
        p_y, w1, b1, nullptr, p_mid, M_TOK, DFF, C_DIM);

    // 7. MLP fc2 + residual -> out
    tf32gemm<3><<<dim3(C_DIM / BN, M_TOK / BM), blk, SMEM_SZ>>>(
        p_mid, w2, b2, p_hs, out, M_TOK, C_DIM, DFF);
}